// round 7
// baseline (speedup 1.0000x reference)
#include <cuda_runtime.h>
#include <math.h>

#define NSEG 4
#define NPIX 256
#define NTHR 1024
#define TSX 16
#define TSY 16
#define NB  148          // one block per SM; all co-resident (grid barrier safe)

#define CAP (1 << 14)
#define MAXTILES 4096
#define MAXPERTILE 2048

__device__ float4 g_pos[CAP];                                // (u, v, thr, z)
__device__ float4 g_con[CAP];                                // (ca, cb, cc, op)
__device__ float4 g_col[CAP];                                // (cr, cg, cb, -)
__device__ int    g_cnt[MAXTILES];                           // zero-init; self-zeroing
__device__ unsigned long long g_list[MAXTILES][MAXPERTILE];
__device__ unsigned int g_bar;                               // monotonic barrier ticket

__global__ __launch_bounds__(NTHR, 1)
void splat_kernel(float* __restrict__ out,
                  const float* __restrict__ means,
                  const float* __restrict__ scales,
                  const float* __restrict__ rots,
                  const float* __restrict__ sh,
                  const float* __restrict__ opac,
                  const float* __restrict__ extr,
                  const float* __restrict__ intr,
                  const int* __restrict__ Hp,
                  const int* __restrict__ Wp,
                  int G, int NV)
{
    int W = *Wp, H = *Hp;
    int ntx = (W + TSX - 1) / TSX, nty = (H + TSY - 1) / TSY;
    int totalTiles = ntx * nty * NV;
    int tid = threadIdx.x;

    // =============== Phase 1: prep + tile binning (all blocks) ===============
    for (int i = blockIdx.x * NTHR + tid; i < G * NV; i += NB * NTHR) {
        int vi = i / G;
        int g  = i - vi * G;

        float Wf = (float)W, Hf = (float)H;
        const float* E = extr + vi * 16;
        const float* K = intr + vi * 9;
        float fx = (K[0] / Wf) * Wf;
        float cx = (K[2] / Wf) * Wf;
        float fy = (K[4] / Hf) * Hf;
        float cy = (K[5] / Hf) * Hf;

        float mx = means[g*3+0], my = means[g*3+1], mz = means[g*3+2];
        float px = E[0]*mx + E[1]*my + E[2]*mz  + E[3];
        float py = E[4]*mx + E[5]*my + E[6]*mz  + E[7];
        float pz = E[8]*mx + E[9]*my + E[10]*mz + E[11];
        float zs = fmaxf(pz, 1e-6f);
        float u = fx * px / zs + cx;
        float v = fy * py / zs + cy;

        float4 q4 = ((const float4*)rots)[g];
        float qw = q4.x, qx = q4.y, qy = q4.z, qz = q4.w;
        float qinv = rsqrtf(qw*qw + qx*qx + qy*qy + qz*qz);
        qw *= qinv; qx *= qinv; qy *= qinv; qz *= qinv;
        float R00 = 1.f - 2.f*(qy*qy + qz*qz), R01 = 2.f*(qx*qy - qw*qz), R02 = 2.f*(qx*qz + qw*qy);
        float R10 = 2.f*(qx*qy + qw*qz), R11 = 1.f - 2.f*(qx*qx + qz*qz), R12 = 2.f*(qy*qz - qw*qx);
        float R20 = 2.f*(qx*qz - qw*qy), R21 = 2.f*(qy*qz + qw*qx), R22 = 1.f - 2.f*(qx*qx + qy*qy);

        float s0 = scales[g*3+0], s1 = scales[g*3+1], s2 = scales[g*3+2];
        float M00=R00*s0, M01=R01*s1, M02=R02*s2;
        float M10=R10*s0, M11=R11*s1, M12=R12*s2;
        float M20=R20*s0, M21=R21*s1, M22=R22*s2;
        float S00 = M00*M00+M01*M01+M02*M02;
        float S01 = M00*M10+M01*M11+M02*M12;
        float S02 = M00*M20+M01*M21+M02*M22;
        float S11 = M10*M10+M11*M11+M12*M12;
        float S12 = M10*M20+M11*M21+M12*M22;
        float S22 = M20*M20+M21*M21+M22*M22;

        float iz  = 1.f / zs;
        float J00 = fx*iz,  J02 = -fx*px*iz*iz;
        float J11 = fy*iz,  J12 = -fy*py*iz*iz;
        float t00 = J00*E[0] + J02*E[8];
        float t01 = J00*E[1] + J02*E[9];
        float t02 = J00*E[2] + J02*E[10];
        float t10 = J11*E[4] + J12*E[8];
        float t11 = J11*E[5] + J12*E[9];
        float t12 = J11*E[6] + J12*E[10];
        float w0 = S00*t00 + S01*t01 + S02*t02;
        float w1 = S01*t00 + S11*t01 + S12*t02;
        float w2 = S02*t00 + S12*t01 + S22*t02;
        float a  = t00*w0 + t01*w1 + t02*w2 + 0.3f;
        float b  = t10*w0 + t11*w1 + t12*w2;
        float x0 = S00*t10 + S01*t11 + S02*t12;
        float x1 = S01*t10 + S11*t11 + S12*t12;
        float x2 = S02*t10 + S12*t11 + S22*t12;
        float d  = t10*x0 + t11*x1 + t12*x2 + 0.3f;

        float det = a*d - b*b;
        float ds  = fmaxf(det, 1e-12f);
        bool valid = (pz > 0.2f) && (det > 1e-12f);
        float op = valid ? opac[g] : 0.f;

        const float SH_C0 = 0.28209479177387814f;
        float cr  = fmaxf(SH_C0 * sh[g*3+0] + 0.5f, 0.f);
        float cg  = fmaxf(SH_C0 * sh[g*3+1] + 0.5f, 0.f);
        float cbl = fmaxf(SH_C0 * sh[g*3+2] + 0.5f, 0.f);

        // Conservative cull radius (exact 1/255 bound via lmax(cov2D))
        float rad = -1.f, thr = 0.f;
        if (op * 255.f > 1.f) {
            float lam = 0.5f*(a+d) + sqrtf(0.25f*(a-d)*(a-d) + b*b);
            float t = logf(255.f * op);
            rad = sqrtf(fmaxf(2.f*t*lam, 0.f)) + 0.05f;
            thr = -t - 1e-4f;
        }

        g_pos[i] = make_float4(u, v, thr, pz);
        g_con[i] = make_float4(-0.5f*(d/ds), (b/ds), -0.5f*(a/ds), op);
        g_col[i] = make_float4(cr, cg, cbl, 0.f);

        if (rad > 0.f) {
            int tx0 = max(0,      (int)ceilf ((u - rad - (float)TSX - 0.01f) / (float)TSX));
            int tx1 = min(ntx-1,  (int)floorf((u + rad + 0.01f) / (float)TSX));
            int ty0 = max(0,      (int)ceilf ((v - rad - (float)TSY - 0.01f) / (float)TSY));
            int ty1 = min(nty-1,  (int)floorf((v + rad + 0.01f) / (float)TSY));

            unsigned int zb = __float_as_uint(pz);
            zb = (zb & 0x80000000u) ? ~zb : (zb | 0x80000000u);
            unsigned long long key = ((unsigned long long)zb << 32) | (unsigned int)g;

            for (int ty = ty0; ty <= ty1; ty++)
                for (int tx = tx0; tx <= tx1; tx++) {
                    int t = vi * ntx * nty + ty * ntx + tx;
                    int slot = atomicAdd(&g_cnt[t], 1);
                    if (slot < MAXPERTILE) g_list[t][slot] = key;
                }
        }
    }

    // =============== Grid barrier (monotonic ticket; replay-safe) ============
    __syncthreads();
    if (tid == 0) {
        __threadfence();
        unsigned int ticket = atomicAdd(&g_bar, 1u);        // 0-based
        unsigned int target = (ticket / NB + 1u) * NB;      // end of this launch's group
        volatile unsigned int* vb = &g_bar;
        while (*vb < target) { }
        __threadfence();
    }
    __syncthreads();

    // =============== Phase 2: per-tile sort + blend ==========================
    extern __shared__ char dsm[];
    float4* s_pos = (float4*)dsm;                  // G*16
    float4* s_con = s_pos + G;                     // G*16
    float4* s_col = s_con + G;                     // G*16
    unsigned long long* s_key = (unsigned long long*)(s_col + G);  // G*8
    int* s_sid = (int*)(s_key + G);                // G*4
    __shared__ float4 segC[NSEG][NPIX];
    __shared__ float  segT[NSEG][NPIX];
    __shared__ int s_cnt;

    int seg = tid >> 8, pix = tid & (NPIX - 1);
    int lx = pix & (TSX - 1), ly = pix >> 4;

    for (int tile = blockIdx.x; tile < totalTiles; tile += NB) {
        int vi = tile / (ntx * nty);
        int t2 = tile - vi * ntx * nty;
        int tx = t2 % ntx, ty = t2 / ntx;
        int base = vi * G;

        __syncthreads();
        if (tid == 0) {
            s_cnt = min(*(volatile int*)&g_cnt[tile], MAXPERTILE);
            g_cnt[tile] = 0;              // restore invariant for next replay
        }
        __syncthreads();
        int cnt = s_cnt;

        for (int i = tid; i < cnt; i += NTHR) s_key[i] = g_list[tile][i];
        __syncthreads();

        // exact rank sort (unique keys -> deterministic permutation)
        for (int i = tid; i < cnt; i += NTHR) {
            unsigned long long k = s_key[i];
            int r = 0;
            for (int j = 0; j < cnt; j++) r += (s_key[j] < k);
            s_sid[r] = base + (int)(unsigned int)k;
        }
        __syncthreads();

        for (int i = tid; i < cnt; i += NTHR) {
            int idx = s_sid[i];
            s_pos[i] = g_pos[idx];
            s_con[i] = g_con[idx];
            s_col[i] = g_col[idx];
        }
        __syncthreads();

        // segment-parallel front-to-back blend
        float pcx = (float)(tx*TSX + lx) + 0.5f;
        float pcy = (float)(ty*TSY + ly) + 0.5f;
        int L = (cnt + NSEG - 1) / NSEG;
        int j0 = seg * L;
        int j1 = min(j0 + L, cnt);

        float T = 1.f, ar = 0.f, ag = 0.f, ab = 0.f, ad = 0.f;
        for (int j = j0; j < j1; j++) {
            float4 p  = s_pos[j];
            float4 cn = s_con[j];
            float du = pcx - p.x, dv = pcy - p.y;
            float power = fmaf(cn.x, du*du, fmaf(cn.z, dv*dv, cn.y*du*dv));
            if (power < p.z) continue;
            power = fminf(power, 0.f);
            float alpha = fminf(cn.w * __expf(power), 0.99f);
            if (alpha >= (1.0f/255.0f)) {
                float4 cl = s_col[j];
                float w = alpha * T;
                ar += w * cl.x; ag += w * cl.y; ab += w * cl.z;
                ad += w * p.w;
                T *= (1.f - alpha);
                if (T < 1e-5f) break;
            }
        }
        segC[seg][pix] = make_float4(ar, ag, ab, ad);
        segT[seg][pix] = T;
        __syncthreads();

        if (seg == 0) {
            float4 C = segC[0][pix];
            float Tacc = segT[0][pix];
            #pragma unroll
            for (int s = 1; s < NSEG; s++) {
                float4 Cs = segC[s][pix];
                C.x += Tacc * Cs.x; C.y += Tacc * Cs.y;
                C.z += Tacc * Cs.z; C.w += Tacc * Cs.w;
                Tacc *= segT[s][pix];
            }
            int px = tx*TSX + lx, py = ty*TSY + ly;
            if (px < W && py < H) {
                ((float4*)out)[(vi * H + py) * W + px] = C;
            }
        }
    }
}

// ---------------------------------------------------------------------------
extern "C" void kernel_launch(void* const* d_in, const int* in_sizes, int n_in,
                              void* d_out, int out_size)
{
    const float* means  = (const float*)d_in[0];
    const float* scales = (const float*)d_in[1];
    const float* rots   = (const float*)d_in[2];
    const float* sh     = (const float*)d_in[3];
    const float* opac   = (const float*)d_in[4];
    const float* extr   = (const float*)d_in[5];
    const float* intr   = (const float*)d_in[6];
    const int*   Hp     = (const int*)d_in[7];
    const int*   Wp     = (const int*)d_in[8];
    float* out = (float*)d_out;

    int G  = in_sizes[4];        // B = 1 for this instance
    int NV = in_sizes[5] / 16;   // B*N views

    size_t dynSmem = (size_t)G * (16 + 16 + 16 + 8 + 4);
    static int attrSet = 0;
    if (!attrSet) {
        cudaFuncSetAttribute(splat_kernel,
                             cudaFuncAttributeMaxDynamicSharedMemorySize,
                             (int)dynSmem);
        attrSet = 1;
    }
    splat_kernel<<<NB, NTHR, dynSmem>>>(out, means, scales, rots, sh, opac,
                                        extr, intr, Hp, Wp, G, NV);
}

// round 8
// speedup vs baseline: 1.3079x; 1.3079x over previous
#include <cuda_runtime.h>
#include <math.h>

#define NSEG 4
#define NPIX 256
#define NTHR 1024
#define TSX 16
#define TSY 16
#define NB  148

// ---------------------------------------------------------------------------
// Single kernel. Each block serves ONE view: computes all G preps into smem
// once, then processes its share of that view's tiles (cull -> rank sort ->
// blend via sorted-index indirection).
// ---------------------------------------------------------------------------
__global__ __launch_bounds__(NTHR, 1)
void splat_kernel(float* __restrict__ out,
                  const float* __restrict__ means,
                  const float* __restrict__ scales,
                  const float* __restrict__ rots,
                  const float* __restrict__ sh,
                  const float* __restrict__ opac,
                  const float* __restrict__ extr,
                  const float* __restrict__ intr,
                  const int* __restrict__ Hp,
                  const int* __restrict__ Wp,
                  int G, int NV)
{
    int W = *Wp, H = *Hp;
    int ntx = (W + TSX - 1) / TSX, nty = (H + TSY - 1) / TSY;
    int tilesPerView = ntx * nty;
    int tid = threadIdx.x;
    int lane = tid & 31;

    extern __shared__ char dsm[];
    float4* s_pos = (float4*)dsm;                   // (u, v, thr, z)   G*16
    float4* s_con = s_pos + G;                      // (ca, cb, cc, op) G*16
    float4* s_col = s_con + G;                      // (cr, cg, cb, -)  G*16
    float*  s_rad = (float*)(s_col + G);            // cull radius      G*4
    unsigned long long* s_key = (unsigned long long*)(s_rad + G);  // G*8
    int* s_sid = (int*)(s_key + G);                 // sorted order     G*4
    __shared__ float4 segC[NSEG][NPIX];
    __shared__ float  segT[NSEG][NPIX];
    __shared__ int s_cnt;

    // ---- view assignment: contiguous block ranges per view ----
    // (valid for NV <= NB; this instance has NV = 2)
    for (int vi = 0; vi < NV; vi++) {
        int b0 = (int)((long long)vi * NB / NV);
        int b1 = (int)((long long)(vi + 1) * NB / NV);
        if ((int)blockIdx.x < b0 || (int)blockIdx.x >= b1) continue;
        int lb = blockIdx.x - b0;
        int nbv = b1 - b0;

        const float* E = extr + vi * 16;
        const float* K = intr + vi * 9;
        float Wf = (float)W, Hf = (float)H;
        float fx = (K[0] / Wf) * Wf;
        float cx = (K[2] / Wf) * Wf;
        float fy = (K[4] / Hf) * Hf;
        float cy = (K[5] / Hf) * Hf;

        // ================= Phase A: prep all G gaussians into smem =========
        for (int g = tid; g < G; g += NTHR) {
            float mx = means[g*3+0], my = means[g*3+1], mz = means[g*3+2];
            float px = E[0]*mx + E[1]*my + E[2]*mz  + E[3];
            float py = E[4]*mx + E[5]*my + E[6]*mz  + E[7];
            float pz = E[8]*mx + E[9]*my + E[10]*mz + E[11];
            float zs = fmaxf(pz, 1e-6f);
            float u = fx * px / zs + cx;
            float v = fy * py / zs + cy;

            float4 q4 = ((const float4*)rots)[g];
            float qw = q4.x, qx = q4.y, qy = q4.z, qz = q4.w;
            float qinv = rsqrtf(qw*qw + qx*qx + qy*qy + qz*qz);
            qw *= qinv; qx *= qinv; qy *= qinv; qz *= qinv;
            float R00 = 1.f - 2.f*(qy*qy + qz*qz), R01 = 2.f*(qx*qy - qw*qz), R02 = 2.f*(qx*qz + qw*qy);
            float R10 = 2.f*(qx*qy + qw*qz), R11 = 1.f - 2.f*(qx*qx + qz*qz), R12 = 2.f*(qy*qz - qw*qx);
            float R20 = 2.f*(qx*qz - qw*qy), R21 = 2.f*(qy*qz + qw*qx), R22 = 1.f - 2.f*(qx*qx + qy*qy);

            float s0 = scales[g*3+0], s1 = scales[g*3+1], s2 = scales[g*3+2];
            float M00=R00*s0, M01=R01*s1, M02=R02*s2;
            float M10=R10*s0, M11=R11*s1, M12=R12*s2;
            float M20=R20*s0, M21=R21*s1, M22=R22*s2;
            float S00 = M00*M00+M01*M01+M02*M02;
            float S01 = M00*M10+M01*M11+M02*M12;
            float S02 = M00*M20+M01*M21+M02*M22;
            float S11 = M10*M10+M11*M11+M12*M12;
            float S12 = M10*M20+M11*M21+M12*M22;
            float S22 = M20*M20+M21*M21+M22*M22;

            float iz  = 1.f / zs;
            float J00 = fx*iz,  J02 = -fx*px*iz*iz;
            float J11 = fy*iz,  J12 = -fy*py*iz*iz;
            float t00 = J00*E[0] + J02*E[8];
            float t01 = J00*E[1] + J02*E[9];
            float t02 = J00*E[2] + J02*E[10];
            float t10 = J11*E[4] + J12*E[8];
            float t11 = J11*E[5] + J12*E[9];
            float t12 = J11*E[6] + J12*E[10];
            float w0 = S00*t00 + S01*t01 + S02*t02;
            float w1 = S01*t00 + S11*t01 + S12*t02;
            float w2 = S02*t00 + S12*t01 + S22*t02;
            float a  = t00*w0 + t01*w1 + t02*w2 + 0.3f;
            float b  = t10*w0 + t11*w1 + t12*w2;
            float x0 = S00*t10 + S01*t11 + S02*t12;
            float x1 = S01*t10 + S11*t11 + S12*t12;
            float x2 = S02*t10 + S12*t11 + S22*t12;
            float d  = t10*x0 + t11*x1 + t12*x2 + 0.3f;

            float det = a*d - b*b;
            float ds  = fmaxf(det, 1e-12f);
            bool valid = (pz > 0.2f) && (det > 1e-12f);
            float op = valid ? opac[g] : 0.f;

            const float SH_C0 = 0.28209479177387814f;
            float cr  = fmaxf(SH_C0 * sh[g*3+0] + 0.5f, 0.f);
            float cg  = fmaxf(SH_C0 * sh[g*3+1] + 0.5f, 0.f);
            float cbl = fmaxf(SH_C0 * sh[g*3+2] + 0.5f, 0.f);

            // conservative cull radius (exact 1/255 bound via lmax(cov2D))
            float rad = -1.f, thr = 0.f;
            if (op * 255.f > 1.f) {
                float lam = 0.5f*(a+d) + sqrtf(0.25f*(a-d)*(a-d) + b*b);
                float t = logf(255.f * op);
                rad = sqrtf(fmaxf(2.f*t*lam, 0.f)) + 0.05f;
                thr = -t - 1e-4f;   // power < thr => alpha < 1/255 guaranteed
            }

            s_pos[g] = make_float4(u, v, thr, pz);
            s_con[g] = make_float4(-0.5f*(d/ds), (b/ds), -0.5f*(a/ds), op);
            s_col[g] = make_float4(cr, cg, cbl, 0.f);
            s_rad[g] = rad;
        }
        __syncthreads();

        // ================= Phase B: this block's tiles =====================
        int seg = tid >> 8, pix = tid & (NPIX - 1);
        int lx = pix & (TSX - 1), ly = pix >> 4;

        for (int t2 = lb; t2 < tilesPerView; t2 += nbv) {
            int tx = t2 % ntx, ty = t2 / ntx;
            float tminx = (float)(tx*TSX), tmaxx = (float)(tx*TSX + TSX);
            float tminy = (float)(ty*TSY), tmaxy = (float)(ty*TSY + TSY);

            __syncthreads();
            if (tid == 0) s_cnt = 0;
            __syncthreads();

            // ---- cull from smem: append (flipped z | idx) keys ----
            for (int g = tid; g < G; g += NTHR) {
                float4 p = s_pos[g];
                float rad = s_rad[g];
                bool keep = (rad > 0.f &&
                             p.x >= tminx - rad && p.x <= tmaxx + rad &&
                             p.y >= tminy - rad && p.y <= tmaxy + rad);
                unsigned m = __ballot_sync(0xffffffffu, keep);
                if (m) {
                    int leader = __ffs(m) - 1;
                    int basep = 0;
                    if (lane == leader) basep = atomicAdd(&s_cnt, __popc(m));
                    basep = __shfl_sync(0xffffffffu, basep, leader);
                    if (keep) {
                        unsigned int zb = __float_as_uint(p.w);
                        zb = (zb & 0x80000000u) ? ~zb : (zb | 0x80000000u);
                        int pp = basep + __popc(m & ((1u << lane) - 1u));
                        s_key[pp] = ((unsigned long long)zb << 32) | (unsigned int)g;
                    }
                }
            }
            __syncthreads();
            int cnt = s_cnt;

            // ---- exact rank sort (unique keys -> deterministic order) ----
            for (int i = tid; i < cnt; i += NTHR) {
                unsigned long long k = s_key[i];
                int r = 0;
                for (int j = 0; j < cnt; j++) r += (s_key[j] < k);
                s_sid[r] = (int)(unsigned int)k;
            }
            __syncthreads();

            // ---- segment-parallel blend via sorted-index indirection ----
            float pcx = (float)(tx*TSX + lx) + 0.5f;
            float pcy = (float)(ty*TSY + ly) + 0.5f;
            int L = (cnt + NSEG - 1) / NSEG;
            int j0 = seg * L;
            int j1 = min(j0 + L, cnt);

            float T = 1.f, ar = 0.f, ag = 0.f, ab = 0.f, ad = 0.f;
            for (int j = j0; j < j1; j++) {
                int idx = s_sid[j];                 // broadcast LDS
                float4 p  = s_pos[idx];
                float4 cn = s_con[idx];
                float du = pcx - p.x, dv = pcy - p.y;
                float power = fmaf(cn.x, du*du, fmaf(cn.z, dv*dv, cn.y*du*dv));
                if (power < p.z) continue;          // alpha < 1/255 guaranteed
                power = fminf(power, 0.f);
                float alpha = fminf(cn.w * __expf(power), 0.99f);
                if (alpha >= (1.0f/255.0f)) {
                    float4 cl = s_col[idx];
                    float w = alpha * T;
                    ar += w * cl.x; ag += w * cl.y; ab += w * cl.z;
                    ad += w * p.w;
                    T *= (1.f - alpha);
                    if (T < 1e-5f) break;           // residual < 1e-5 absolute
                }
            }
            segC[seg][pix] = make_float4(ar, ag, ab, ad);
            segT[seg][pix] = T;
            __syncthreads();

            // ---- combine segments front-to-back + store ----
            if (seg == 0) {
                float4 C = segC[0][pix];
                float Tacc = segT[0][pix];
                #pragma unroll
                for (int s = 1; s < NSEG; s++) {
                    float4 Cs = segC[s][pix];
                    C.x += Tacc * Cs.x; C.y += Tacc * Cs.y;
                    C.z += Tacc * Cs.z; C.w += Tacc * Cs.w;
                    Tacc *= segT[s][pix];
                }
                int px = tx*TSX + lx, py = ty*TSY + ly;
                if (px < W && py < H) {
                    ((float4*)out)[(vi * H + py) * W + px] = C;
                }
            }
        }
        __syncthreads();   // block done with this view's smem
    }
}

// ---------------------------------------------------------------------------
extern "C" void kernel_launch(void* const* d_in, const int* in_sizes, int n_in,
                              void* d_out, int out_size)
{
    const float* means  = (const float*)d_in[0];
    const float* scales = (const float*)d_in[1];
    const float* rots   = (const float*)d_in[2];
    const float* sh     = (const float*)d_in[3];
    const float* opac   = (const float*)d_in[4];
    const float* extr   = (const float*)d_in[5];
    const float* intr   = (const float*)d_in[6];
    const int*   Hp     = (const int*)d_in[7];
    const int*   Wp     = (const int*)d_in[8];
    float* out = (float*)d_out;

    int G  = in_sizes[4];        // B = 1 for this instance
    int NV = in_sizes[5] / 16;   // B*N views

    // pos + con + col + rad + key + sid = 16*3 + 4 + 8 + 4 = 64 B per gaussian
    size_t dynSmem = (size_t)G * 64;
    static int attrSet = 0;
    if (!attrSet) {
        cudaFuncSetAttribute(splat_kernel,
                             cudaFuncAttributeMaxDynamicSharedMemorySize,
                             (int)dynSmem);
        attrSet = 1;
    }
    splat_kernel<<<NB, NTHR, dynSmem>>>(out, means, scales, rots, sh, opac,
                                        extr, intr, Hp, Wp, G, NV);
}